// round 7
// baseline (speedup 1.0000x reference)
#include <cuda_runtime.h>

// ---------------------------------------------------------------------------
// LBP histogram kernel, GB300 sm_103a — round 5
// R2 memory structure (default-cached loads, depth-3 lookahead) + fused
// last-block finalize. img: [16,3,1024,1024] fp32 -> out: [1,256] fp32.
// ---------------------------------------------------------------------------

#define IMG_H 1024
#define IMG_W 1024
#define HW (IMG_H * IMG_W)

#define THREADS 256
#define BLOCKS 444                 // 148 SMs * 3 blocks (64 KB smem each)
#define CHUNK 32                   // rows per task
#define N_TASKS (16 * 8 * 32)      // 16 imgs * 8 strips(128 col) * 32 chunks

__device__ unsigned int g_count[256];
__device__ unsigned int g_ticket;
__device__ unsigned int g_done;

struct Row { float4 g; float l, r; };

__device__ __forceinline__ float gray1(float r, float g, float b) {
    return fmaf(0.114f, b, fmaf(0.587f, g, 0.299f * r));
}

// Load one gray row (4 px/lane) for a 128-column strip, halo cols + zero pad.
// Default caching: priming rows and halo columns are re-read by neighboring
// tasks and should hit L2.
__device__ __forceinline__ Row load_row4(const float* __restrict__ base,
                                         int r, int rmax, int c0, int lane) {
    Row o;
    o.g = make_float4(0.f, 0.f, 0.f, 0.f);
    float h = 0.f;
    if ((unsigned)r < (unsigned)IMG_H && r <= rmax) {
        const float* q = base + (size_t)r * IMG_W;
        const float4* p = (const float4*)(q + c0) + lane;
        float4 cr = p[0];
        float4 cg = p[HW >> 2];
        float4 cb = p[HW >> 1];
        o.g.x = gray1(cr.x, cg.x, cb.x);
        o.g.y = gray1(cr.y, cg.y, cb.y);
        o.g.z = gray1(cr.z, cg.z, cb.z);
        o.g.w = gray1(cr.w, cg.w, cb.w);
        // merged halo: lane0 -> col c0-1, lane31 -> col c0+128
        int hc = (lane == 0) ? (c0 - 1) : (c0 + 128);
        if (((lane == 0) | (lane == 31)) && (unsigned)hc < (unsigned)IMG_W)
            h = gray1(q[hc], q[hc + HW], q[hc + 2 * HW]);
    }
    float sl = __shfl_up_sync(0xffffffffu, o.g.w, 1);
    float sr = __shfl_down_sync(0xffffffffu, o.g.x, 1);
    o.l = (lane == 0) ? h : sl;
    o.r = (lane == 31) ? h : sr;
    return o;
}

__device__ __forceinline__ void upd(unsigned char* __restrict__ hist, int tid,
                                    float c, float tl, float t, float tr,
                                    float l, float rr, float bl, float b,
                                    float br) {
    unsigned code;
    code  = (tr >= c) ?   1u : 0u;   // top-right
    code |= (rr >= c) ?   2u : 0u;   // right
    code |= (br >= c) ?   4u : 0u;   // bottom-right
    code |= (b  >= c) ?   8u : 0u;   // bottom
    code |= (bl >= c) ?  16u : 0u;   // bottom-left
    code |= (l  >= c) ?  32u : 0u;   // left
    code |= (tl >= c) ?  64u : 0u;   // top-left
    code |= (t  >= c) ? 128u : 0u;   // top
    // swizzle: different codes in a lane-quad -> different banks; equal codes
    // -> same word, distinct bytes (merge). Thread-exclusive per code block.
    hist[(code << 8) + ((tid + (code << 2)) & 255)]++;
}

extern "C" __global__ void __launch_bounds__(THREADS, 3)
lbp_main(const float* __restrict__ img, float* __restrict__ out) {
    extern __shared__ unsigned char hist[];   // 64 KB
    __shared__ float sh[256];
    __shared__ int s_last;
    const int tid = threadIdx.x;
    const int lane = tid & 31;

    uint4* h4 = (uint4*)hist;
#pragma unroll
    for (int i = 0; i < 16; i++)
        h4[tid + i * THREADS] = make_uint4(0u, 0u, 0u, 0u);
    __syncthreads();

    for (;;) {
        unsigned t;
        if (lane == 0) t = atomicAdd(&g_ticket, 1u);
        t = __shfl_sync(0xffffffffu, t, 0);
        if (t >= N_TASKS) break;

        const int chunk = t & 31;            // row chunk
        const int strip = (t >> 5) & 7;      // 128-col strip
        const int b = t >> 8;                // image
        const int c0 = strip << 7;
        const int r0 = chunk * CHUNK;
        const int rmax = r0 + CHUNK;         // deepest row actually needed
        const float* base = img + (size_t)b * 3 * HW;

        // 4-row sliding window, 2-row load lookahead (R2 scheme)
        Row top = load_row4(base, r0 - 1, rmax, c0, lane);
        Row mid = load_row4(base, r0,     rmax, c0, lane);
        Row bot = load_row4(base, r0 + 1, rmax, c0, lane);
        Row nx  = load_row4(base, r0 + 2, rmax, c0, lane);

#pragma unroll 4
        for (int r = r0; r < r0 + CHUNK; r++) {
            Row nx2 = load_row4(base, r + 3, rmax, c0, lane);

            upd(hist, tid, mid.g.x, top.l,   top.g.x, top.g.y,
                mid.l,   mid.g.y, bot.l,   bot.g.x, bot.g.y);
            upd(hist, tid, mid.g.y, top.g.x, top.g.y, top.g.z,
                mid.g.x, mid.g.z, bot.g.x, bot.g.y, bot.g.z);
            upd(hist, tid, mid.g.z, top.g.y, top.g.z, top.g.w,
                mid.g.y, mid.g.w, bot.g.y, bot.g.z, bot.g.w);
            upd(hist, tid, mid.g.w, top.g.z, top.g.w, top.r,
                mid.g.z, mid.r,   bot.g.z, bot.g.w, bot.r);

            top = mid; mid = bot; bot = nx; nx = nx2;
        }
    }
    __syncthreads();

    // Block reduction: thread tid sums code block tid (64 words, rotated
    // start -> conflict-free). Swizzle is a per-code bijection of bytes,
    // so block sums are unchanged.
    const unsigned int* h32 = (const unsigned int*)hist;
    unsigned int sum = 0;
    const int wbase = tid << 6;
#pragma unroll 8
    for (int j = 0; j < 64; j++) {
        unsigned int w = h32[wbase + ((tid + j) & 63)];
        sum = __dp4a(w, 0x01010101u, sum);
    }
    atomicAdd(&g_count[tid], sum);

    // ---- last-block finalize (fused standardization) ----
    __threadfence();
    if (tid == 0) {
        unsigned d = atomicAdd(&g_done, 1u);
        s_last = (d == BLOCKS - 1);
    }
    __syncthreads();
    if (!s_last) return;

    // read-and-zero counters so every graph replay starts clean
    float h = (float)atomicExch(&g_count[tid], 0u);

    sh[tid] = h;
    __syncthreads();
    for (int s = 128; s > 0; s >>= 1) {
        if (tid < s) sh[tid] += sh[tid + s];
        __syncthreads();
    }
    const float mean = sh[0] * (1.0f / 256.0f);
    __syncthreads();

    const float d = h - mean;
    sh[tid] = d * d;
    __syncthreads();
    for (int s = 128; s > 0; s >>= 1) {
        if (tid < s) sh[tid] += sh[tid + s];
        __syncthreads();
    }
    const float stdv = sqrtf(sh[0] * (1.0f / 255.0f));   // ddof = 1
    out[tid] = d / stdv;

    if (tid == 0) {
        g_ticket = 0u;   // reset work queue for next replay
        g_done = 0u;
    }
}

extern "C" void kernel_launch(void* const* d_in, const int* in_sizes, int n_in,
                              void* d_out, int out_size) {
    (void)in_sizes; (void)n_in; (void)out_size;
    const float* img = (const float*)d_in[0];
    float* out = (float*)d_out;

    cudaFuncSetAttribute(lbp_main, cudaFuncAttributeMaxDynamicSharedMemorySize,
                         65536);
    lbp_main<<<BLOCKS, THREADS, 65536>>>(img, out);
}

// round 8
// speedup vs baseline: 1.1410x; 1.1410x over previous
#include <cuda_runtime.h>

// ---------------------------------------------------------------------------
// LBP histogram kernel, GB300 sm_103a — round 7
// img: [16,3,1024,1024] fp32 -> out: [1,256] fp32 standardized histogram
// One segment per warp (perfect static balance), 2-deep raw register prefetch,
// sign-bit LBP codes, swizzled per-thread byte histograms, fused finalize.
// ---------------------------------------------------------------------------

#define IMG_H 1024
#define IMG_W 1024
#define HW (IMG_H * IMG_W)

#define THREADS 256
#define BLOCKS 444                  // 148 SMs * 3 blocks = one full wave
#define WARPS_TOTAL (BLOCKS * 8)    // 3552
// 128 (image,strip) columns; 96 columns split into 28 row-segments, 32 into 27:
// 96*28 + 32*27 = 3552 segments == warps. Every warp does exactly one segment.
#define COLS_28 96

__device__ unsigned int g_count[256];
__device__ unsigned int g_done;

struct Row { float4 g; float l, r; };
struct Raw { float4 r, g, b; float hr, hg, hb; };

__device__ __forceinline__ float gray1(float r, float g, float b) {
    return fmaf(0.114f, b, fmaf(0.587f, g, 0.299f * r));
}

// Issue loads for one row (no dependent math). Warp-uniform row predicate.
__device__ __forceinline__ Raw load_raw(const float* __restrict__ base,
                                        int x, int rb, int c0, int lane) {
    Raw o;
    o.r = o.g = o.b = make_float4(0.f, 0.f, 0.f, 0.f);
    o.hr = o.hg = o.hb = 0.f;
    if ((unsigned)x < (unsigned)IMG_H && x <= rb) {
        const float* q = base + (size_t)x * IMG_W;
        const float4* p = (const float4*)(q + c0) + lane;
        o.r = p[0];
        o.g = p[HW >> 2];
        o.b = p[HW >> 1];
        int hc = (lane == 0) ? (c0 - 1) : (c0 + 128);
        if (((lane == 0) | (lane == 31)) && (unsigned)hc < (unsigned)IMG_W) {
            o.hr = q[hc]; o.hg = q[hc + HW]; o.hb = q[hc + 2 * HW];
        }
    }
    return o;
}

// Convert a raw row (loaded >=1 iteration ago) to gray + neighbor shuffles.
__device__ __forceinline__ Row conv(const Raw& a, int lane) {
    Row o;
    o.g.x = gray1(a.r.x, a.g.x, a.b.x);
    o.g.y = gray1(a.r.y, a.g.y, a.b.y);
    o.g.z = gray1(a.r.z, a.g.z, a.b.z);
    o.g.w = gray1(a.r.w, a.g.w, a.b.w);
    float h = gray1(a.hr, a.hg, a.hb);      // 0 when no halo
    float sl = __shfl_up_sync(0xffffffffu, o.g.w, 1);
    float sr = __shfl_down_sync(0xffffffffu, o.g.x, 1);
    o.l = (lane == 0) ? h : sl;
    o.r = (lane == 31) ? h : sr;
    return o;
}

// sign(n - c): 1 iff n < c. All grays are >= 0 and equal operands give +0,
// so this matches (n >= c) exactly; code bit = 1 - sign.
__device__ __forceinline__ unsigned sbit(float n, float c) {
    return __float_as_uint(n - c) >> 31;
}

__device__ __forceinline__ void upd(unsigned char* __restrict__ hist, int tid,
                                    float c, float tl, float t, float tr,
                                    float l, float rr, float bl, float b,
                                    float br) {
    unsigned m = sbit(tr, c)
               | (sbit(rr, c) << 1)
               | (sbit(br, c) << 2)
               | (sbit(b,  c) << 3)
               | (sbit(bl, c) << 4)
               | (sbit(l,  c) << 5)
               | (sbit(tl, c) << 6)
               | (sbit(t,  c) << 7);
    unsigned code = m ^ 255u;
    // swizzle: different codes in a lane-quad -> different banks; equal codes
    // -> same word, distinct bytes (merge). Thread-exclusive per code block.
    hist[(code << 8) + ((tid + (code << 2)) & 255u)]++;
}

extern "C" __global__ void __launch_bounds__(THREADS, 3)
lbp_main(const float* __restrict__ img, float* __restrict__ out) {
    extern __shared__ unsigned char hist[];   // 64 KB
    __shared__ float sh[256];
    __shared__ int s_last;
    const int tid = threadIdx.x;
    const int lane = tid & 31;

    uint4* h4 = (uint4*)hist;
#pragma unroll
    for (int i = 0; i < 16; i++)
        h4[tid + i * THREADS] = make_uint4(0u, 0u, 0u, 0u);
    __syncthreads();

    // ---- one statically assigned row-segment per warp ----
    const int w = blockIdx.x * 8 + (tid >> 5);    // 0..3551
    int col, n, s;
    if (w < COLS_28 * 28) { col = w / 28; n = 28; s = w - col * 28; }
    else { int w2 = w - COLS_28 * 28; col = COLS_28 + w2 / 27; n = 27;
           s = w2 - (col - COLS_28) * 27; }
    const int ra = (s * IMG_H) / n;               // first center row
    const int rb = ((s + 1) * IMG_H) / n;         // one past last center row
    const int c0 = (col & 7) << 7;                // strip column base
    const float* base = img + (size_t)(col >> 3) * 3 * HW;

    // ---- prologue: prime window + 2-deep raw prefetch ----
    Raw A = load_raw(base, ra - 1, rb, c0, lane);
    Raw B = load_raw(base, ra,     rb, c0, lane);
    Row top = conv(A, lane);
    A = load_raw(base, ra + 1, rb, c0, lane);
    Row mid = conv(B, lane);
    B = load_raw(base, ra + 2, rb, c0, lane);
    Row bot = conv(A, lane);
    A = load_raw(base, ra + 3, rb, c0, lane);
    // invariant at loop top for center r: B = raw(r+2), A = raw(r+3)

#pragma unroll 2
    for (int r = ra; r < rb; r++) {
        upd(hist, tid, mid.g.x, top.l,   top.g.x, top.g.y,
            mid.l,   mid.g.y, bot.l,   bot.g.x, bot.g.y);
        upd(hist, tid, mid.g.y, top.g.x, top.g.y, top.g.z,
            mid.g.x, mid.g.z, bot.g.x, bot.g.y, bot.g.z);
        upd(hist, tid, mid.g.z, top.g.y, top.g.z, top.g.w,
            mid.g.y, mid.g.w, bot.g.y, bot.g.z, bot.g.w);
        upd(hist, tid, mid.g.w, top.g.z, top.g.w, top.r,
            mid.g.z, mid.r,   bot.g.z, bot.g.w, bot.r);

        Row nx = conv(B, lane);     // loaded ~2 iterations ago
        B = A;
        A = load_raw(base, r + 4, rb, c0, lane);
        top = mid; mid = bot; bot = nx;
    }
    __syncthreads();

    // Block reduction: thread tid sums code block tid (64 words, rotated
    // start -> conflict-free). Swizzle is a per-code bijection of bytes,
    // so block sums are unchanged.
    const unsigned int* h32 = (const unsigned int*)hist;
    unsigned int sum = 0;
    const int wbase = tid << 6;
#pragma unroll 8
    for (int j = 0; j < 64; j++) {
        unsigned int v = h32[wbase + ((tid + j) & 63)];
        sum = __dp4a(v, 0x01010101u, sum);
    }
    atomicAdd(&g_count[tid], sum);

    // ---- last-block finalize (fused standardization) ----
    __threadfence();
    if (tid == 0) {
        unsigned d = atomicAdd(&g_done, 1u);
        s_last = (d == BLOCKS - 1);
    }
    __syncthreads();
    if (!s_last) return;

    // read-and-zero counters so every graph replay starts clean
    float h = (float)atomicExch(&g_count[tid], 0u);

    sh[tid] = h;
    __syncthreads();
    for (int s2 = 128; s2 > 0; s2 >>= 1) {
        if (tid < s2) sh[tid] += sh[tid + s2];
        __syncthreads();
    }
    const float mean = sh[0] * (1.0f / 256.0f);
    __syncthreads();

    const float d = h - mean;
    sh[tid] = d * d;
    __syncthreads();
    for (int s2 = 128; s2 > 0; s2 >>= 1) {
        if (tid < s2) sh[tid] += sh[tid + s2];
        __syncthreads();
    }
    const float stdv = sqrtf(sh[0] * (1.0f / 255.0f));   // ddof = 1
    out[tid] = d / stdv;

    if (tid == 0) g_done = 0u;   // reset for next graph replay
}

extern "C" void kernel_launch(void* const* d_in, const int* in_sizes, int n_in,
                              void* d_out, int out_size) {
    (void)in_sizes; (void)n_in; (void)out_size;
    const float* img = (const float*)d_in[0];
    float* out = (float*)d_out;

    cudaFuncSetAttribute(lbp_main, cudaFuncAttributeMaxDynamicSharedMemorySize,
                         65536);
    lbp_main<<<BLOCKS, THREADS, 65536>>>(img, out);
}

// round 9
// speedup vs baseline: 1.2199x; 1.0691x over previous
#include <cuda_runtime.h>

// ---------------------------------------------------------------------------
// LBP histogram kernel, GB300 sm_103a — round 8
// img: [16,3,1024,1024] fp32 -> out: [1,256] fp32 standardized histogram
// One segment per warp, pointer-carried rows, peeled guards, unroll-6 steady
// state (kills struct-copy MOVs), 2-deep raw prefetch, swizzled per-thread
// byte histograms, fused finalize.
// ---------------------------------------------------------------------------

#define IMG_H 1024
#define IMG_W 1024
#define HW (IMG_H * IMG_W)
#define W4 (IMG_W >> 2)

#define THREADS 256
#define BLOCKS 444                  // 148 SMs * 3 blocks = one full wave
// 128 (image,strip) columns; 96 cols -> 28 row-segments, 32 cols -> 27:
// 96*28 + 32*27 = 3552 segments == total warps. One segment per warp.
#define COLS_28 96

__device__ unsigned int g_count[256];
__device__ unsigned int g_done;

struct Row { float4 g; float l, r; };
struct Raw { float4 r, g, b; float hr, hg, hb; };

__device__ __forceinline__ float gray1(float r, float g, float b) {
    return fmaf(0.114f, b, fmaf(0.587f, g, 0.299f * r));
}

// Steady-state row load: unconditional bulk, predicated halo (warp-constant).
__device__ __forceinline__ Raw load_fast(const float4* __restrict__ p,
                                         const float* __restrict__ qh,
                                         bool ph) {
    Raw o;
    o.r = p[0];
    o.g = p[HW >> 2];
    o.b = p[HW >> 1];
    o.hr = o.hg = o.hb = 0.f;
    if (ph) { o.hr = qh[0]; o.hg = qh[HW]; o.hb = qh[2 * HW]; }
    return o;
}

// Edge row load: zero-fills out-of-range / out-of-segment rows.
__device__ __forceinline__ Raw load_guard(const float4* __restrict__ p,
                                          const float* __restrict__ qh,
                                          bool ph, int x, int rb) {
    Raw o;
    o.r = o.g = o.b = make_float4(0.f, 0.f, 0.f, 0.f);
    o.hr = o.hg = o.hb = 0.f;
    if ((unsigned)x < (unsigned)IMG_H && x <= rb) {
        o.r = p[0];
        o.g = p[HW >> 2];
        o.b = p[HW >> 1];
        if (ph) { o.hr = qh[0]; o.hg = qh[HW]; o.hb = qh[2 * HW]; }
    }
    return o;
}

// Convert a raw row (loaded ~2 iterations ago) to gray + neighbor shuffles.
__device__ __forceinline__ Row conv(const Raw& a, int lane) {
    Row o;
    o.g.x = gray1(a.r.x, a.g.x, a.b.x);
    o.g.y = gray1(a.r.y, a.g.y, a.b.y);
    o.g.z = gray1(a.r.z, a.g.z, a.b.z);
    o.g.w = gray1(a.r.w, a.g.w, a.b.w);
    float h = gray1(a.hr, a.hg, a.hb);      // 0 when no halo
    float sl = __shfl_up_sync(0xffffffffu, o.g.w, 1);
    float sr = __shfl_down_sync(0xffffffffu, o.g.x, 1);
    o.l = (lane == 0) ? h : sl;
    o.r = (lane == 31) ? h : sr;
    return o;
}

// sign(n - c): 1 iff n < c (grays >= 0, x-x = +0, so matches n >= c exactly).
__device__ __forceinline__ unsigned sbit(float n, float c) {
    return __float_as_uint(n - c) >> 31;
}

__device__ __forceinline__ void upd(unsigned char* __restrict__ hist, int tid,
                                    float c, float tl, float t, float tr,
                                    float l, float rr, float bl, float b,
                                    float br) {
    unsigned m = sbit(tr, c)
               | (sbit(rr, c) << 1)
               | (sbit(br, c) << 2)
               | (sbit(b,  c) << 3)
               | (sbit(bl, c) << 4)
               | (sbit(l,  c) << 5)
               | (sbit(tl, c) << 6)
               | (sbit(t,  c) << 7);
    unsigned code = m ^ 255u;
    // swizzle: different codes in a lane-quad -> different banks; equal codes
    // -> same word, distinct bytes (merge). Thread-exclusive per code block.
    hist[(code << 8) + ((tid + (code << 2)) & 255u)]++;
}

#define DO4UPDS()                                                        \
    do {                                                                 \
        upd(hist, tid, mid.g.x, top.l,   top.g.x, top.g.y,               \
            mid.l,   mid.g.y, bot.l,   bot.g.x, bot.g.y);                \
        upd(hist, tid, mid.g.y, top.g.x, top.g.y, top.g.z,               \
            mid.g.x, mid.g.z, bot.g.x, bot.g.y, bot.g.z);                \
        upd(hist, tid, mid.g.z, top.g.y, top.g.z, top.g.w,               \
            mid.g.y, mid.g.w, bot.g.y, bot.g.z, bot.g.w);                \
        upd(hist, tid, mid.g.w, top.g.z, top.g.w, top.r,                 \
            mid.g.z, mid.r,   bot.g.z, bot.g.w, bot.r);                  \
    } while (0)

extern "C" __global__ void __launch_bounds__(THREADS, 3)
lbp_main(const float* __restrict__ img, float* __restrict__ out) {
    extern __shared__ unsigned char hist[];   // 64 KB
    __shared__ float sh[256];
    __shared__ int s_last;
    const int tid = threadIdx.x;
    const int lane = tid & 31;

    uint4* h4 = (uint4*)hist;
#pragma unroll
    for (int i = 0; i < 16; i++)
        h4[tid + i * THREADS] = make_uint4(0u, 0u, 0u, 0u);
    __syncthreads();

    // ---- one statically assigned row-segment per warp ----
    const int w = blockIdx.x * 8 + (tid >> 5);    // 0..3551
    int col, nseg, s;
    if (w < COLS_28 * 28) { col = w / 28; nseg = 28; s = w - col * 28; }
    else { int w2 = w - COLS_28 * 28; col = COLS_28 + w2 / 27; nseg = 27;
           s = w2 - (col - COLS_28) * 27; }
    const int ra = (s * IMG_H) / nseg;            // first center row
    const int rb = ((s + 1) * IMG_H) / nseg;      // one past last center row
    const int c0 = (col & 7) << 7;                // strip column base
    const float* chan = img + (size_t)(col >> 3) * 3 * HW;

    // warp-constant halo predicate + pointers (row ra-1)
    const bool ph = ((lane == 0) & (c0 > 0)) | ((lane == 31) & (c0 + 128 < IMG_W));
    const int hc = (lane == 0) ? (c0 - 1) : (c0 + 128);
    const float4* p = (const float4*)(chan + c0) + (long)(ra - 1) * W4 + lane;
    const float* qh = chan + (long)(ra - 1) * IMG_W + hc;

    // ---- prologue: prime window + 2-deep raw prefetch (guarded rows) ----
    Raw A = load_guard(p, qh, ph, ra - 1, rb); p += W4; qh += IMG_W;
    Raw B = load_guard(p, qh, ph, ra,     rb); p += W4; qh += IMG_W;
    Row top = conv(A, lane);
    A = load_guard(p, qh, ph, ra + 1, rb); p += W4; qh += IMG_W;
    Row mid = conv(B, lane);
    B = load_guard(p, qh, ph, ra + 2, rb); p += W4; qh += IMG_W;
    Row bot = conv(A, lane);
    A = load_guard(p, qh, ph, ra + 3, rb); p += W4; qh += IMG_W;
    // invariant at loop top (center r): B = raw(r+2), A = raw(r+3),
    // p/qh point at row r+4.

    int r = ra;
    const int rmain = rb - 4;     // rows r+4 <= rb-1 are unconditionally valid
#pragma unroll 6
    for (; r < rmain; r++) {
        DO4UPDS();
        Row nx = conv(B, lane);
        B = A;
        A = load_fast(p, qh, ph); p += W4; qh += IMG_W;
        top = mid; mid = bot; bot = nx;
    }
    for (; r < rb; r++) {         // last 4 centers: guarded loads
        DO4UPDS();
        Row nx = conv(B, lane);
        B = A;
        A = load_guard(p, qh, ph, r + 4, rb); p += W4; qh += IMG_W;
        top = mid; mid = bot; bot = nx;
    }
    __syncthreads();

    // Block reduction: thread tid sums code block tid (64 words, rotated
    // start -> conflict-free). Swizzle is a per-code bijection of bytes,
    // so block sums are unchanged.
    const unsigned int* h32 = (const unsigned int*)hist;
    unsigned int sum = 0;
    const int wbase = tid << 6;
#pragma unroll 8
    for (int j = 0; j < 64; j++) {
        unsigned int v = h32[wbase + ((tid + j) & 63)];
        sum = __dp4a(v, 0x01010101u, sum);
    }
    atomicAdd(&g_count[tid], sum);

    // ---- last-block finalize (fused standardization) ----
    __threadfence();
    if (tid == 0) {
        unsigned d = atomicAdd(&g_done, 1u);
        s_last = (d == BLOCKS - 1);
    }
    __syncthreads();
    if (!s_last) return;

    // read-and-zero counters so every graph replay starts clean
    float h = (float)atomicExch(&g_count[tid], 0u);

    sh[tid] = h;
    __syncthreads();
    for (int s2 = 128; s2 > 0; s2 >>= 1) {
        if (tid < s2) sh[tid] += sh[tid + s2];
        __syncthreads();
    }
    const float mean = sh[0] * (1.0f / 256.0f);
    __syncthreads();

    const float d = h - mean;
    sh[tid] = d * d;
    __syncthreads();
    for (int s2 = 128; s2 > 0; s2 >>= 1) {
        if (tid < s2) sh[tid] += sh[tid + s2];
        __syncthreads();
    }
    const float stdv = sqrtf(sh[0] * (1.0f / 255.0f));   // ddof = 1
    out[tid] = d / stdv;

    if (tid == 0) g_done = 0u;   // reset for next graph replay
}

extern "C" void kernel_launch(void* const* d_in, const int* in_sizes, int n_in,
                              void* d_out, int out_size) {
    (void)in_sizes; (void)n_in; (void)out_size;
    const float* img = (const float*)d_in[0];
    float* out = (float*)d_out;

    cudaFuncSetAttribute(lbp_main, cudaFuncAttributeMaxDynamicSharedMemorySize,
                         65536);
    lbp_main<<<BLOCKS, THREADS, 65536>>>(img, out);
}

// round 13
// speedup vs baseline: 1.2340x; 1.0116x over previous
#include <cuda_runtime.h>

// ---------------------------------------------------------------------------
// LBP histogram kernel, GB300 sm_103a — round 12
// img: [16,3,1024,1024] fp32 -> out: [1,256] fp32 standardized histogram
// One segment per warp, pointer-carried rows, peeled guards, unroll-6 steady
// state, PTX prmt sign-replicate (template-constant selector) + DP4A code
// builder, XOR-swizzled per-thread byte histograms, fused finalize.
// ---------------------------------------------------------------------------

#define IMG_H 1024
#define IMG_W 1024
#define HW (IMG_H * IMG_W)
#define W4 (IMG_W >> 2)

#define THREADS 256
#define BLOCKS 444                  // 148 SMs * 3 blocks = one full wave
// 128 (image,strip) columns; 96 cols -> 28 row-segments, 32 cols -> 27:
// 96*28 + 32*27 = 3552 segments == total warps. One segment per warp.
#define COLS_28 96

__device__ unsigned int g_count[256];
__device__ unsigned int g_done;

struct Row { float4 g; float l, r; };
struct Raw { float4 r, g, b; float hr, hg, hb; };

__device__ __forceinline__ float gray1(float r, float g, float b) {
    return fmaf(0.114f, b, fmaf(0.587f, g, 0.299f * r));
}

// PTX prmt.b32 default mode: selector nibble 0x8|i replicates the sign (msb)
// of source byte i across the destination byte (PTX ISA guaranteed).
// SEL as template parameter -> integral constant expression for the "n"
// constraint (a plain function argument is not, even when inlined).
template <unsigned SEL>
__device__ __forceinline__ unsigned prmt(unsigned a, unsigned b) {
    unsigned d;
    asm("prmt.b32 %0, %1, %2, %3;" : "=r"(d) : "r"(a), "r"(b), "n"(SEL));
    return d;
}

// Steady-state row load: unconditional bulk, predicated halo (warp-constant).
__device__ __forceinline__ Raw load_fast(const float4* __restrict__ p,
                                         const float* __restrict__ qh,
                                         bool ph) {
    Raw o;
    o.r = p[0];
    o.g = p[HW >> 2];
    o.b = p[HW >> 1];
    o.hr = o.hg = o.hb = 0.f;
    if (ph) { o.hr = qh[0]; o.hg = qh[HW]; o.hb = qh[2 * HW]; }
    return o;
}

// Edge row load: zero-fills out-of-range / out-of-segment rows.
__device__ __forceinline__ Raw load_guard(const float4* __restrict__ p,
                                          const float* __restrict__ qh,
                                          bool ph, int x, int rb) {
    Raw o;
    o.r = o.g = o.b = make_float4(0.f, 0.f, 0.f, 0.f);
    o.hr = o.hg = o.hb = 0.f;
    if ((unsigned)x < (unsigned)IMG_H && x <= rb) {
        o.r = p[0];
        o.g = p[HW >> 2];
        o.b = p[HW >> 1];
        if (ph) { o.hr = qh[0]; o.hg = qh[HW]; o.hb = qh[2 * HW]; }
    }
    return o;
}

// Convert a raw row (loaded ~2 iterations ago) to gray + neighbor shuffles.
__device__ __forceinline__ Row conv(const Raw& a, int lane) {
    Row o;
    o.g.x = gray1(a.r.x, a.g.x, a.b.x);
    o.g.y = gray1(a.r.y, a.g.y, a.b.y);
    o.g.z = gray1(a.r.z, a.g.z, a.b.z);
    o.g.w = gray1(a.r.w, a.g.w, a.b.w);
    float h = gray1(a.hr, a.hg, a.hb);      // 0 when no halo
    float sl = __shfl_up_sync(0xffffffffu, o.g.w, 1);
    float sr = __shfl_down_sync(0xffffffffu, o.g.x, 1);
    o.l = (lane == 0) ? h : sl;
    o.r = (lane == 31) ? h : sr;
    return o;
}

// LBP code via prmt sign-replication + DP4A byte-sum.
// bit_i = (n_i >= c) = NOT sign(n_i - c); grays >= 0, x-x = +0, so exact.
__device__ __forceinline__ void upd(unsigned char* __restrict__ hist, int tid,
                                    float c, float tl, float t, float tr,
                                    float l, float rr, float bl, float b,
                                    float br) {
    unsigned d0 = __float_as_uint(tr - c);   // bit 0
    unsigned d1 = __float_as_uint(rr - c);   // bit 1
    unsigned d2 = __float_as_uint(br - c);   // bit 2
    unsigned d3 = __float_as_uint(b  - c);   // bit 3
    unsigned d4 = __float_as_uint(bl - c);   // bit 4
    unsigned d5 = __float_as_uint(l  - c);   // bit 5
    unsigned d6 = __float_as_uint(tl - c);   // bit 6
    unsigned d7 = __float_as_uint(t  - c);   // bit 7
    // byte = 0xFF iff diff < 0 (sign-replicate of each diff's MSB byte)
    unsigned p01 = prmt<0x00FBu>(d0, d1);    // b0=sgn d0, b1=sgn d1
    unsigned p23 = prmt<0xFB00u>(d2, d3);    // b2=sgn d2, b3=sgn d3
    unsigned mlo = prmt<0x7610u>(p01, p23);  // [s0,s1,s2,s3]
    unsigned p45 = prmt<0x00FBu>(d4, d5);
    unsigned p67 = prmt<0xFB00u>(d6, d7);
    unsigned mhi = prmt<0x7610u>(p45, p67);  // [s4,s5,s6,s7]
    // code bit i set iff NOT sign: (~m) & weight, then byte-sum via dp4a
    unsigned lo = ~mlo & 0x08040201u;
    unsigned hi = ~mhi & 0x80402010u;
    unsigned code = __dp4a(lo, 0x01010101u, __dp4a(hi, 0x01010101u, 0u));
    // XOR swizzle: equal codes in a lane-quad -> same word, distinct bytes
    // (merge); different codes -> spread banks. Bijection per code block.
    hist[(code << 8) + (tid ^ ((code << 2) & 255u))]++;
}

#define DO4UPDS()                                                        \
    do {                                                                 \
        upd(hist, tid, mid.g.x, top.l,   top.g.x, top.g.y,               \
            mid.l,   mid.g.y, bot.l,   bot.g.x, bot.g.y);                \
        upd(hist, tid, mid.g.y, top.g.x, top.g.y, top.g.z,               \
            mid.g.x, mid.g.z, bot.g.x, bot.g.y, bot.g.z);                \
        upd(hist, tid, mid.g.z, top.g.y, top.g.z, top.g.w,               \
            mid.g.y, mid.g.w, bot.g.y, bot.g.z, bot.g.w);                \
        upd(hist, tid, mid.g.w, top.g.z, top.g.w, top.r,                 \
            mid.g.z, mid.r,   bot.g.z, bot.g.w, bot.r);                  \
    } while (0)

extern "C" __global__ void __launch_bounds__(THREADS, 3)
lbp_main(const float* __restrict__ img, float* __restrict__ out) {
    extern __shared__ unsigned char hist[];   // 64 KB
    __shared__ float sh[256];
    __shared__ int s_last;
    const int tid = threadIdx.x;
    const int lane = tid & 31;

    uint4* h4 = (uint4*)hist;
#pragma unroll
    for (int i = 0; i < 16; i++)
        h4[tid + i * THREADS] = make_uint4(0u, 0u, 0u, 0u);
    __syncthreads();

    // ---- one statically assigned row-segment per warp ----
    const int w = blockIdx.x * 8 + (tid >> 5);    // 0..3551
    int col, nseg, s;
    if (w < COLS_28 * 28) { col = w / 28; nseg = 28; s = w - col * 28; }
    else { int w2 = w - COLS_28 * 28; col = COLS_28 + w2 / 27; nseg = 27;
           s = w2 - (col - COLS_28) * 27; }
    const int ra = (s * IMG_H) / nseg;            // first center row
    const int rb = ((s + 1) * IMG_H) / nseg;      // one past last center row
    const int c0 = (col & 7) << 7;                // strip column base
    const float* chan = img + (size_t)(col >> 3) * 3 * HW;

    // warp-constant halo predicate + pointers (row ra-1)
    const bool ph = ((lane == 0) & (c0 > 0)) | ((lane == 31) & (c0 + 128 < IMG_W));
    const int hc = (lane == 0) ? (c0 - 1) : (c0 + 128);
    const float4* p = (const float4*)(chan + c0) + (long)(ra - 1) * W4 + lane;
    const float* qh = chan + (long)(ra - 1) * IMG_W + hc;

    // ---- prologue: prime window + 2-deep raw prefetch (guarded rows) ----
    Raw A = load_guard(p, qh, ph, ra - 1, rb); p += W4; qh += IMG_W;
    Raw B = load_guard(p, qh, ph, ra,     rb); p += W4; qh += IMG_W;
    Row top = conv(A, lane);
    A = load_guard(p, qh, ph, ra + 1, rb); p += W4; qh += IMG_W;
    Row mid = conv(B, lane);
    B = load_guard(p, qh, ph, ra + 2, rb); p += W4; qh += IMG_W;
    Row bot = conv(A, lane);
    A = load_guard(p, qh, ph, ra + 3, rb); p += W4; qh += IMG_W;
    // invariant at loop top (center r): B = raw(r+2), A = raw(r+3),
    // p/qh point at row r+4.

    int r = ra;
    const int rmain = rb - 4;     // rows r+4 <= rb-1 are unconditionally valid
#pragma unroll 6
    for (; r < rmain; r++) {
        DO4UPDS();
        Row nx = conv(B, lane);
        B = A;
        A = load_fast(p, qh, ph); p += W4; qh += IMG_W;
        top = mid; mid = bot; bot = nx;
    }
    for (; r < rb; r++) {         // last 4 centers: guarded loads
        DO4UPDS();
        Row nx = conv(B, lane);
        B = A;
        A = load_guard(p, qh, ph, r + 4, rb); p += W4; qh += IMG_W;
        top = mid; mid = bot; bot = nx;
    }
    __syncthreads();

    // Block reduction: thread tid sums code block tid (64 words, rotated
    // start -> conflict-free). Swizzle is a per-code bijection of bytes,
    // so block sums are unchanged.
    const unsigned int* h32 = (const unsigned int*)hist;
    unsigned int sum = 0;
    const int wbase = tid << 6;
#pragma unroll 8
    for (int j = 0; j < 64; j++) {
        unsigned int v = h32[wbase + ((tid + j) & 63)];
        sum = __dp4a(v, 0x01010101u, sum);
    }
    atomicAdd(&g_count[tid], sum);

    // ---- last-block finalize (fused standardization) ----
    __threadfence();
    if (tid == 0) {
        unsigned d = atomicAdd(&g_done, 1u);
        s_last = (d == BLOCKS - 1);
    }
    __syncthreads();
    if (!s_last) return;

    // read-and-zero counters so every graph replay starts clean
    float h = (float)atomicExch(&g_count[tid], 0u);

    sh[tid] = h;
    __syncthreads();
    for (int s2 = 128; s2 > 0; s2 >>= 1) {
        if (tid < s2) sh[tid] += sh[tid + s2];
        __syncthreads();
    }
    const float mean = sh[0] * (1.0f / 256.0f);
    __syncthreads();

    const float d = h - mean;
    sh[tid] = d * d;
    __syncthreads();
    for (int s2 = 128; s2 > 0; s2 >>= 1) {
        if (tid < s2) sh[tid] += sh[tid + s2];
        __syncthreads();
    }
    const float stdv = sqrtf(sh[0] * (1.0f / 255.0f));   // ddof = 1
    out[tid] = d / stdv;

    if (tid == 0) g_done = 0u;   // reset for next graph replay
}

extern "C" void kernel_launch(void* const* d_in, const int* in_sizes, int n_in,
                              void* d_out, int out_size) {
    (void)in_sizes; (void)n_in; (void)out_size;
    const float* img = (const float*)d_in[0];
    float* out = (float*)d_out;

    cudaFuncSetAttribute(lbp_main, cudaFuncAttributeMaxDynamicSharedMemorySize,
                         65536);
    lbp_main<<<BLOCKS, THREADS, 65536>>>(img, out);
}